// round 14
// baseline (speedup 1.0000x reference)
#include <cuda_runtime.h>
#include <cuda_fp16.h>
#include <cstdint>
#include <cstddef>

// Block-diagonal batched GEMM via fp16 HMMA (mma.sync m16n8k16), single
// product (A, B fp16-rounded; measured rel_err 2.94e-4 < 1e-3).
// Round 14: single fused kernel (A converted inline from fp32 mats; no prep
// kernel, no cp.async), one barrier per chunk. 128x128 tiles, BK=64.

#define NGROUPS 15
#define NCOLS   10752
#define NTILES  23

__constant__ int c_g[NGROUPS]     = {64,128,256,96,160,224,192,288,320,112,80,48,32,16,32};
__constant__ int c_start[NGROUPS] = {0,64,192,448,544,704,928,1120,1408,1728,1840,1920,1968,2000,2016};
__constant__ int c_kpad[NGROUPS]  = {64,128,256,128,192,256,192,320,320,128,128,64,64,64,64};
// 128-row tiles, heaviest groups first
__constant__ int c_tileg[NTILES]  = {8,8,8, 7,7,7, 2,2, 5,5, 4,4, 6,6, 1, 3, 9, 10, 0, 11, 12, 13, 14};
__constant__ int c_tiler[NTILES]  = {0,128,256, 0,128,256, 0,128, 0,128, 0,128, 0,128, 0,0,0,0,0,0,0,0,0};

struct MatPtrs { const float* p[NGROUPS]; };

// ---------------- PTX helpers (compute_103-legal) ----------------
__device__ __forceinline__ uint32_t smem_u32(const void* p) {
    uint32_t a;
    asm("{ .reg .u64 t; cvta.to.shared.u64 t, %1; cvt.u32.u64 %0, t; }" : "=r"(a) : "l"(p));
    return a;
}
__device__ __forceinline__ void ldsm_x4(uint32_t* r, uint32_t addr) {
    asm volatile("ldmatrix.sync.aligned.m8n8.x4.shared.b16 {%0,%1,%2,%3}, [%4];"
        : "=r"(r[0]), "=r"(r[1]), "=r"(r[2]), "=r"(r[3]) : "r"(addr));
}
__device__ __forceinline__ void ldsm_x4_t(uint32_t* r, uint32_t addr) {
    asm volatile("ldmatrix.sync.aligned.m8n8.x4.trans.shared.b16 {%0,%1,%2,%3}, [%4];"
        : "=r"(r[0]), "=r"(r[1]), "=r"(r[2]), "=r"(r[3]) : "r"(addr));
}
__device__ __forceinline__ void mma_f16(float* c, const uint32_t* a, uint32_t b0, uint32_t b1) {
    asm volatile("mma.sync.aligned.m16n8k16.row.col.f32.f16.f16.f32 "
        "{%0,%1,%2,%3}, {%4,%5,%6,%7}, {%8,%9}, {%0,%1,%2,%3};"
        : "+f"(c[0]), "+f"(c[1]), "+f"(c[2]), "+f"(c[3])
        : "r"(a[0]), "r"(a[1]), "r"(a[2]), "r"(a[3]), "r"(b0), "r"(b1));
}
__device__ __forceinline__ uint2 cvt4(float4 v) {
    __half2 h01 = __floats2half2_rn(v.x, v.y);
    __half2 h23 = __floats2half2_rn(v.z, v.w);
    uint2 u;
    u.x = *reinterpret_cast<uint32_t*>(&h01);
    u.y = *reinterpret_cast<uint32_t*>(&h23);
    return u;
}

// ---------------- smem layout ----------------
#define APITCH 72    // fp16: 64 k + 8 pad  -> 144B rows (conflict-free)
#define BPITCH 136   // fp16: 128 n + 8 pad -> 272B rows (conflict-free)
#define OFF_A  0
#define OFF_B  18432                   // 128 * 144
#define STAGE_BYTES 35840              // 18432 + 64*272
#define SMEM_TOTAL  (2 * STAGE_BYTES)  // 71680 -> 2 CTAs/SM

__global__ __launch_bounds__(256, 2)
void bdiag_hmma_kernel(const float* __restrict__ x, float* __restrict__ out,
                       MatPtrs mats)
{
    extern __shared__ char smem[];
    const uint32_t sb = smem_u32(smem);

    const int tid    = threadIdx.x;
    const int lane   = tid & 31;
    const int wid    = tid >> 5;
    const int warp_m = wid >> 1;   // 4 warps over M (128 rows, 32 each)
    const int warp_n = wid & 1;    // 2 warps over N (128 cols, 64 each)

    const int tile  = blockIdx.y;
    const int grp   = c_tileg[tile];
    const int K     = c_g[grp];
    const int Kpad  = c_kpad[grp];
    const int row0  = c_tiler[tile];
    const int col0  = blockIdx.x * 128;
    const int xbase = c_start[grp];
    const int nch   = Kpad >> 6;

    const float* __restrict__ Mg = mats.p[grp];

    // A ownership: 2048 float4 slots (128 rows x 16 segs of 4 fl); 8/thread.
    //   idx = tid + j*256 -> row = idx>>4, seg = idx&15
    const int a_seg = tid & 15;
    const int a_r0  = tid >> 4;    // + j*16
    // B ownership: 2048 float4 slots (64 k x 32 c4); 8/thread.
    //   idx = tid + j*256 -> k = idx>>5, c4 = idx&31
    const int b_k0 = tid >> 5;     // + j*8
    const int b_c4 = tid & 31;

    // Inline A load+convert+store: fp32 mat -> fp16 smem (zeros when masked)
    auto convLoadA = [&](int ch, uint32_t off) {
        const int kc0 = ch << 6;
        #pragma unroll
        for (int j = 0; j < 8; j++) {
            const int row = a_r0 + j * 16;
            const int gr  = row0 + row;
            const int gk  = kc0 + a_seg * 4;
            float4 v = make_float4(0.f, 0.f, 0.f, 0.f);
            if (gr < K && gk < K)
                v = *reinterpret_cast<const float4*>(Mg + (size_t)gr * K + gk);
            *reinterpret_cast<uint2*>(
                smem + off + OFF_A + row * 144 + a_seg * 8) = cvt4(v);
        }
    };
    // Inline B load+convert+store: fp32 x -> fp16 smem
    auto convLoadB = [&](int ch, uint32_t off) {
        const int kc0 = ch << 6;
        #pragma unroll
        for (int j = 0; j < 8; j++) {
            const int k = b_k0 + j * 8;
            float4 v = make_float4(0.f, 0.f, 0.f, 0.f);
            if (kc0 + k < K)
                v = *reinterpret_cast<const float4*>(
                    x + (size_t)(xbase + kc0 + k) * NCOLS + col0 + b_c4 * 4);
            *reinterpret_cast<uint2*>(
                smem + off + OFF_B + k * 272 + b_c4 * 8) = cvt4(v);
        }
    };

    float acc[2][8][4];
    #pragma unroll
    for (int mi = 0; mi < 2; mi++)
        #pragma unroll
        for (int ni = 0; ni < 8; ni++)
            #pragma unroll
            for (int q = 0; q < 4; q++) acc[mi][ni][q] = 0.0f;

    const int lr = lane & 15;
    const int lc = lane >> 4;

    // ---- prologue: stage 0
    convLoadA(0, 0);
    convLoadB(0, 0);

    for (int ch = 0; ch < nch; ch++) {
        __syncthreads();   // STS(ch) visible; MMA(ch-1) reads of other stage done

        const uint32_t sbase = sb + (ch & 1) * STAGE_BYTES;
        #pragma unroll
        for (int ks = 0; ks < 4; ks++) {
            uint32_t af[2][4];
            #pragma unroll
            for (int mi = 0; mi < 2; mi++) {
                const uint32_t ao = sbase + OFF_A +
                    ((warp_m * 32 + mi * 16 + lr) * APITCH + ks * 16 + lc * 8) * 2;
                ldsm_x4(af[mi], ao);
            }
            uint32_t bf[4][4];
            #pragma unroll
            for (int p = 0; p < 4; p++) {
                const uint32_t bo = sbase + OFF_B +
                    ((ks * 16 + lr) * BPITCH + warp_n * 64 + p * 16 + lc * 8) * 2;
                ldsm_x4_t(bf[p], bo);
            }
            #pragma unroll
            for (int mi = 0; mi < 2; mi++)
                #pragma unroll
                for (int ni = 0; ni < 8; ni++) {
                    const int p = ni >> 1, s = (ni & 1) * 2;
                    mma_f16(acc[mi][ni], af[mi], bf[p][s], bf[p][s + 1]);
                }
        }

        // load+convert next chunk into the other stage (safe: its readers
        // finished before the sync at the top of this iteration)
        if (ch + 1 < nch) {
            const uint32_t off = ((ch + 1) & 1) * STAGE_BYTES;
            convLoadA(ch + 1, off);
            convLoadB(ch + 1, off);
        }
    }

    // ---- epilogue: masked float2 stores straight from fragments
    const int rbase = row0 + warp_m * 32 + (lane >> 2);
    const int cb    = col0 + warp_n * 64 + (lane & 3) * 2;
    #pragma unroll
    for (int mi = 0; mi < 2; mi++) {
        #pragma unroll
        for (int half = 0; half < 2; half++) {
            const int row = rbase + mi * 16 + half * 8;
            if (row < K) {
                float* dst = out + (size_t)(xbase + row) * NCOLS + cb;
                #pragma unroll
                for (int ni = 0; ni < 8; ni++)
                    *reinterpret_cast<float2*>(dst + ni * 8) =
                        make_float2(acc[mi][ni][half * 2], acc[mi][ni][half * 2 + 1]);
            }
        }
    }
}

extern "C" void kernel_launch(void* const* d_in, const int* in_sizes, int n_in,
                              void* d_out, int out_size)
{
    const float* x = (const float*)d_in[0];
    float* out = (float*)d_out;

    MatPtrs mats;
    for (int i = 0; i < NGROUPS; i++) mats.p[i] = (const float*)d_in[1 + i];

    cudaFuncSetAttribute(bdiag_hmma_kernel,
                         cudaFuncAttributeMaxDynamicSharedMemorySize, SMEM_TOTAL);

    bdiag_hmma_kernel<<<dim3(NCOLS / 128, NTILES), 256, SMEM_TOTAL>>>(x, out, mats);
}

// round 15
// speedup vs baseline: 1.2413x; 1.2413x over previous
#include <cuda_runtime.h>
#include <cuda_fp16.h>
#include <cstdint>
#include <cstddef>

// Block-diagonal batched GEMM via fp16 HMMA (mma.sync m16n8k16), single
// product (A, B fp16-rounded; measured rel_err 2.94e-4 < 1e-3).
// Round 15: R13 base + half-prefetched B (hides DRAM latency behind the MMA
// phase) + cheap 2D-grid prep kernel.

#define NGROUPS 15
#define NCOLS   10752
#define NTILES  23

__constant__ int c_g[NGROUPS]     = {64,128,256,96,160,224,192,288,320,112,80,48,32,16,32};
__constant__ int c_start[NGROUPS] = {0,64,192,448,544,704,928,1120,1408,1728,1840,1920,1968,2000,2016};
__constant__ int c_kpad[NGROUPS]  = {64,128,256,128,192,256,192,320,320,128,128,64,64,64,64};
__constant__ int c_aoff[NGROUPS]  = {0,4096,20480,86016,98304,129024,186368,223232,315392,417792,432128,442368,445440,447488,448512};
// 128-row tiles, heaviest groups first
__constant__ int c_tileg[NTILES]  = {8,8,8, 7,7,7, 2,2, 5,5, 4,4, 6,6, 1, 3, 9, 10, 0, 11, 12, 13, 14};
__constant__ int c_tiler[NTILES]  = {0,128,256, 0,128,256, 0,128, 0,128, 0,128, 0,128, 0,0,0,0,0,0,0,0,0};

// Preconverted block matrices (fp16, zero K-padding), zero-initialized.
__device__ __half g_A[450560];

struct MatPtrs { const float* p[NGROUPS]; };

// ---------------- PTX helpers (compute_103-legal) ----------------
__device__ __forceinline__ uint32_t smem_u32(const void* p) {
    uint32_t a;
    asm("{ .reg .u64 t; cvta.to.shared.u64 t, %1; cvt.u32.u64 %0, t; }" : "=r"(a) : "l"(p));
    return a;
}
__device__ __forceinline__ void cp16(uint32_t dst, const void* src) {
    asm volatile("cp.async.cg.shared.global [%0], [%1], 16;" :: "r"(dst), "l"(src));
}
#define CP_COMMIT() asm volatile("cp.async.commit_group;" ::: "memory")
#define CP_WAIT1()  asm volatile("cp.async.wait_group 1;" ::: "memory")
#define CP_WAIT0()  asm volatile("cp.async.wait_group 0;" ::: "memory")

__device__ __forceinline__ void ldsm_x4(uint32_t* r, uint32_t addr) {
    asm volatile("ldmatrix.sync.aligned.m8n8.x4.shared.b16 {%0,%1,%2,%3}, [%4];"
        : "=r"(r[0]), "=r"(r[1]), "=r"(r[2]), "=r"(r[3]) : "r"(addr));
}
__device__ __forceinline__ void ldsm_x4_t(uint32_t* r, uint32_t addr) {
    asm volatile("ldmatrix.sync.aligned.m8n8.x4.trans.shared.b16 {%0,%1,%2,%3}, [%4];"
        : "=r"(r[0]), "=r"(r[1]), "=r"(r[2]), "=r"(r[3]) : "r"(addr));
}
__device__ __forceinline__ void mma_f16(float* c, const uint32_t* a, uint32_t b0, uint32_t b1) {
    asm volatile("mma.sync.aligned.m16n8k16.row.col.f32.f16.f16.f32 "
        "{%0,%1,%2,%3}, {%4,%5,%6,%7}, {%8,%9}, {%0,%1,%2,%3};"
        : "+f"(c[0]), "+f"(c[1]), "+f"(c[2]), "+f"(c[3])
        : "r"(a[0]), "r"(a[1]), "r"(a[2]), "r"(a[3]), "r"(b0), "r"(b1));
}
__device__ __forceinline__ uint2 cvt4(float4 v) {
    __half2 h01 = __floats2half2_rn(v.x, v.y);
    __half2 h23 = __floats2half2_rn(v.z, v.w);
    uint2 u;
    u.x = *reinterpret_cast<uint32_t*>(&h01);
    u.y = *reinterpret_cast<uint32_t*>(&h23);
    return u;
}

// ---------------- prep: round mats to fp16 (K zero-padded), 2D grid ----------------
__global__ void conv_mats_kernel(MatPtrs mats) {
    const int g   = blockIdx.y;
    const int G   = c_g[g];
    const int Kp  = c_kpad[g];
    const int n   = G * Kp;
    const int idx = blockIdx.x * 256 + threadIdx.x;
    if (idx >= n) return;
    const int m = idx / Kp;
    const int k = idx - m * Kp;
    float v = (k < G) ? mats.p[g][m * G + k] : 0.0f;
    g_A[c_aoff[g] + idx] = __float2half_rn(v);
}

// ---------------- main fp16 HMMA kernel ----------------
#define APITCH 72    // fp16: 64 k + 8 pad  -> 144B rows (conflict-free)
#define BPITCH 136   // fp16: 128 n + 8 pad -> 272B rows (conflict-free)
#define OFF_A  0
#define OFF_B  18432                   // 128 * 144
#define STAGE_BYTES 35840              // 18432 + 64*272
#define SMEM_TOTAL  (2 * STAGE_BYTES)  // 71680 -> 2 CTAs/SM

__global__ __launch_bounds__(256, 2)
void bdiag_hmma_kernel(const float* __restrict__ x, float* __restrict__ out)
{
    extern __shared__ char smem[];
    const uint32_t sb = smem_u32(smem);

    const int tid    = threadIdx.x;
    const int lane   = tid & 31;
    const int wid    = tid >> 5;
    const int warp_m = wid >> 1;   // 4 warps over M (128 rows, 32 each)
    const int warp_n = wid & 1;    // 2 warps over N (128 cols, 64 each)

    const int tile  = blockIdx.y;
    const int grp   = c_tileg[tile];
    const int K     = c_g[grp];
    const int Kpad  = c_kpad[grp];
    const int row0  = c_tiler[tile];
    const int col0  = blockIdx.x * 128;
    const int xbase = c_start[grp];

    const __half* __restrict__ Ag = g_A + c_aoff[grp];

    // A cp.async ownership: 1024 slots (128 rows x 8 segs of 16B), 4/thread.
    const int a_seg = tid & 7;
    const int a_r0  = tid >> 3;    // + j*32
    #pragma unroll
    for (int j = 0; j < 4; j++) {
        if (row0 + a_r0 + j * 32 >= K) {   // zero-prefill masked rows, both stages
            const uint32_t d = (a_r0 + j * 32) * 144 + a_seg * 16;
            const uint4 z = make_uint4(0, 0, 0, 0);
            *reinterpret_cast<uint4*>(smem + d + OFF_A) = z;
            *reinterpret_cast<uint4*>(smem + d + STAGE_BYTES + OFF_A) = z;
        }
    }

    // B ownership: 8 slots/thread; slot idx = tid + j*256; k = idx>>5, c4 = idx&31
    const int b_k0 = tid >> 5;      // + j*8
    const int b_c4 = tid & 31;
    const int nch  = Kpad >> 6;

    auto issueA = [&](int ch, uint32_t sbuf) {
        const int kc0 = ch << 6;
        #pragma unroll
        for (int j = 0; j < 4; j++) {
            const int rr = a_r0 + j * 32;
            if (row0 + rr < K)
                cp16(sbuf + rr * 144 + a_seg * 16 + OFF_A,
                     Ag + (size_t)(row0 + rr) * Kpad + kc0 + a_seg * 8);
        }
    };
    // B load for slots [j0, j0+cnt)
    auto ldgB = [&](int ch, int j0, float4* r, int cnt) {
        const int kc0 = ch << 6;
        for (int j = 0; j < cnt; j++) {
            const int k = b_k0 + (j0 + j) * 8;
            r[j] = make_float4(0.f, 0.f, 0.f, 0.f);
            if (kc0 + k < K)
                r[j] = *reinterpret_cast<const float4*>(
                    x + (size_t)(xbase + kc0 + k) * NCOLS + col0 + b_c4 * 4);
        }
    };
    auto stsB = [&](uint32_t off, int j0, const float4* r, int cnt) {
        for (int j = 0; j < cnt; j++) {
            const int k = b_k0 + (j0 + j) * 8;
            *reinterpret_cast<uint2*>(
                smem + off + OFF_B + k * 272 + b_c4 * 8) = cvt4(r[j]);
        }
    };

    float acc[2][8][4];
    #pragma unroll
    for (int mi = 0; mi < 2; mi++)
        #pragma unroll
        for (int ni = 0; ni < 8; ni++)
            #pragma unroll
            for (int q = 0; q < 4; q++) acc[mi][ni][q] = 0.0f;

    const int lr = lane & 15;
    const int lc = lane >> 4;

    // ---- prologue: stage 0 (A async; B inline, both halves)
    issueA(0, sb);
    CP_COMMIT();
    {
        float4 r[4];
        ldgB(0, 0, r, 4); stsB(0, 0, r, 4);
        ldgB(0, 4, r, 4); stsB(0, 4, r, 4);
    }

    for (int ch = 0; ch < nch; ch++) {
        if (ch + 1 < nch) {
            issueA(ch + 1, sb + ((ch + 1) & 1) * STAGE_BYTES);
            CP_COMMIT();
            CP_WAIT1();      // A(ch) landed (in-order group completion)
        } else {
            CP_WAIT0();      // last chunk: drain everything
        }
        __syncthreads();     // stage ch fully visible (A async + B STS)

        // prefetch first half of B(ch+1) NOW; MMA phase hides the latency.
        float4 rp[4];
        const bool more = (ch + 1 < nch);
        if (more) ldgB(ch + 1, 0, rp, 4);

        const uint32_t sbase = sb + (ch & 1) * STAGE_BYTES;
        #pragma unroll
        for (int ks = 0; ks < 4; ks++) {
            uint32_t af[2][4];
            #pragma unroll
            for (int mi = 0; mi < 2; mi++) {
                const uint32_t ao = sbase + OFF_A +
                    ((warp_m * 32 + mi * 16 + lr) * APITCH + ks * 16 + lc * 8) * 2;
                ldsm_x4(af[mi], ao);
            }
            uint32_t bf[4][4];
            #pragma unroll
            for (int p = 0; p < 4; p++) {
                const uint32_t bo = sbase + OFF_B +
                    ((ks * 16 + lr) * BPITCH + warp_n * 64 + p * 16 + lc * 8) * 2;
                ldsm_x4_t(bf[p], bo);
            }
            #pragma unroll
            for (int mi = 0; mi < 2; mi++)
                #pragma unroll
                for (int ni = 0; ni < 8; ni++) {
                    const int p = ni >> 1, s = (ni & 1) * 2;
                    mma_f16(acc[mi][ni], af[mi], bf[p][s], bf[p][s + 1]);
                }
        }

        // store prefetched half, then load+convert+store second half inline
        if (more) {
            const uint32_t off = ((ch + 1) & 1) * STAGE_BYTES;
            stsB(off, 0, rp, 4);
            float4 r2[4];
            ldgB(ch + 1, 4, r2, 4);
            stsB(off, 4, r2, 4);
        }

        __syncthreads();     // stage reads done + next-stage B STS ordered
    }

    // ---- epilogue: masked float2 stores straight from fragments
    const int rbase = row0 + warp_m * 32 + (lane >> 2);
    const int cb    = col0 + warp_n * 64 + (lane & 3) * 2;
    #pragma unroll
    for (int mi = 0; mi < 2; mi++) {
        #pragma unroll
        for (int half = 0; half < 2; half++) {
            const int row = rbase + mi * 16 + half * 8;
            if (row < K) {
                float* dst = out + (size_t)(xbase + row) * NCOLS + cb;
                #pragma unroll
                for (int ni = 0; ni < 8; ni++)
                    *reinterpret_cast<float2*>(dst + ni * 8) =
                        make_float2(acc[mi][ni][half * 2], acc[mi][ni][half * 2 + 1]);
            }
        }
    }
}

extern "C" void kernel_launch(void* const* d_in, const int* in_sizes, int n_in,
                              void* d_out, int out_size)
{
    const float* x = (const float*)d_in[0];
    float* out = (float*)d_out;

    MatPtrs mats;
    for (int i = 0; i < NGROUPS; i++) mats.p[i] = (const float*)d_in[1 + i];

    cudaFuncSetAttribute(bdiag_hmma_kernel,
                         cudaFuncAttributeMaxDynamicSharedMemorySize, SMEM_TOTAL);

    conv_mats_kernel<<<dim3(400, NGROUPS), 256>>>(mats);
    bdiag_hmma_kernel<<<dim3(NCOLS / 128, NTILES), 256, SMEM_TOTAL>>>(x, out);
}

// round 16
// speedup vs baseline: 1.5945x; 1.2845x over previous
#include <cuda_runtime.h>
#include <cuda_fp16.h>
#include <cstdint>
#include <cstddef>

// Block-diagonal batched GEMM via fp16 HMMA (mma.sync m16n8k16), single
// product (A, B fp16-rounded; measured rel_err 2.94e-4 < 1e-3).
// Round 16: R15 main kernel (best: 57.1us) + compact 1D vectorized prep
// kernel (440 blocks) to restore the small inter-kernel overhead.

#define NGROUPS 15
#define NCOLS   10752
#define NTILES  23

__constant__ int c_g[NGROUPS]     = {64,128,256,96,160,224,192,288,320,112,80,48,32,16,32};
__constant__ int c_start[NGROUPS] = {0,64,192,448,544,704,928,1120,1408,1728,1840,1920,1968,2000,2016};
__constant__ int c_kpad[NGROUPS]  = {64,128,256,128,192,256,192,320,320,128,128,64,64,64,64};
__constant__ int c_aoff[NGROUPS]  = {0,4096,20480,86016,98304,129024,186368,223232,315392,417792,432128,442368,445440,447488,448512};
// 128-row tiles, heaviest groups first
__constant__ int c_tileg[NTILES]  = {8,8,8, 7,7,7, 2,2, 5,5, 4,4, 6,6, 1, 3, 9, 10, 0, 11, 12, 13, 14};
__constant__ int c_tiler[NTILES]  = {0,128,256, 0,128,256, 0,128, 0,128, 0,128, 0,128, 0,0,0,0,0,0,0,0,0};

// Preconverted block matrices (fp16, zero K-padding), zero-initialized.
__device__ __half g_A[450560];

struct MatPtrs { const float* p[NGROUPS]; };

// ---------------- PTX helpers (compute_103-legal) ----------------
__device__ __forceinline__ uint32_t smem_u32(const void* p) {
    uint32_t a;
    asm("{ .reg .u64 t; cvta.to.shared.u64 t, %1; cvt.u32.u64 %0, t; }" : "=r"(a) : "l"(p));
    return a;
}
__device__ __forceinline__ void cp16(uint32_t dst, const void* src) {
    asm volatile("cp.async.cg.shared.global [%0], [%1], 16;" :: "r"(dst), "l"(src));
}
#define CP_COMMIT() asm volatile("cp.async.commit_group;" ::: "memory")
#define CP_WAIT1()  asm volatile("cp.async.wait_group 1;" ::: "memory")
#define CP_WAIT0()  asm volatile("cp.async.wait_group 0;" ::: "memory")

__device__ __forceinline__ void ldsm_x4(uint32_t* r, uint32_t addr) {
    asm volatile("ldmatrix.sync.aligned.m8n8.x4.shared.b16 {%0,%1,%2,%3}, [%4];"
        : "=r"(r[0]), "=r"(r[1]), "=r"(r[2]), "=r"(r[3]) : "r"(addr));
}
__device__ __forceinline__ void ldsm_x4_t(uint32_t* r, uint32_t addr) {
    asm volatile("ldmatrix.sync.aligned.m8n8.x4.trans.shared.b16 {%0,%1,%2,%3}, [%4];"
        : "=r"(r[0]), "=r"(r[1]), "=r"(r[2]), "=r"(r[3]) : "r"(addr));
}
__device__ __forceinline__ void mma_f16(float* c, const uint32_t* a, uint32_t b0, uint32_t b1) {
    asm volatile("mma.sync.aligned.m16n8k16.row.col.f32.f16.f16.f32 "
        "{%0,%1,%2,%3}, {%4,%5,%6,%7}, {%8,%9}, {%0,%1,%2,%3};"
        : "+f"(c[0]), "+f"(c[1]), "+f"(c[2]), "+f"(c[3])
        : "r"(a[0]), "r"(a[1]), "r"(a[2]), "r"(a[3]), "r"(b0), "r"(b1));
}
__device__ __forceinline__ uint2 cvt4(float4 v) {
    __half2 h01 = __floats2half2_rn(v.x, v.y);
    __half2 h23 = __floats2half2_rn(v.z, v.w);
    uint2 u;
    u.x = *reinterpret_cast<uint32_t*>(&h01);
    u.y = *reinterpret_cast<uint32_t*>(&h23);
    return u;
}

// ---------------- prep: round mats to fp16 (K zero-padded), 4 elems/thread ----------------
__global__ void conv_mats_kernel(MatPtrs mats) {
    const int i4 = (blockIdx.x * 256 + threadIdx.x) * 4;   // all c_aoff, Kp mult of 4
    if (i4 >= 450560) return;
    int g = 0;
    #pragma unroll
    for (int i = 1; i < NGROUPS; i++) if (i4 >= c_aoff[i]) g = i;
    const int local = i4 - c_aoff[g];
    const int Kp = c_kpad[g], G = c_g[g];
    const int m = local / Kp;
    const int k = local - m * Kp;
    const float* row = mats.p[g] + (size_t)m * G;
    float4 v;
    v.x = (k + 0 < G) ? row[k + 0] : 0.0f;
    v.y = (k + 1 < G) ? row[k + 1] : 0.0f;
    v.z = (k + 2 < G) ? row[k + 2] : 0.0f;
    v.w = (k + 3 < G) ? row[k + 3] : 0.0f;
    *reinterpret_cast<uint2*>(g_A + i4) = cvt4(v);
}

// ---------------- main fp16 HMMA kernel (identical to R15 = 57.1us) ----------------
#define APITCH 72    // fp16: 64 k + 8 pad  -> 144B rows (conflict-free)
#define BPITCH 136   // fp16: 128 n + 8 pad -> 272B rows (conflict-free)
#define OFF_A  0
#define OFF_B  18432                   // 128 * 144
#define STAGE_BYTES 35840              // 18432 + 64*272
#define SMEM_TOTAL  (2 * STAGE_BYTES)  // 71680 -> 2 CTAs/SM

__global__ __launch_bounds__(256, 2)
void bdiag_hmma_kernel(const float* __restrict__ x, float* __restrict__ out)
{
    extern __shared__ char smem[];
    const uint32_t sb = smem_u32(smem);

    const int tid    = threadIdx.x;
    const int lane   = tid & 31;
    const int wid    = tid >> 5;
    const int warp_m = wid >> 1;   // 4 warps over M (128 rows, 32 each)
    const int warp_n = wid & 1;    // 2 warps over N (128 cols, 64 each)

    const int tile  = blockIdx.y;
    const int grp   = c_tileg[tile];
    const int K     = c_g[grp];
    const int Kpad  = c_kpad[grp];
    const int row0  = c_tiler[tile];
    const int col0  = blockIdx.x * 128;
    const int xbase = c_start[grp];

    const __half* __restrict__ Ag = g_A + c_aoff[grp];

    // A cp.async ownership: 1024 slots (128 rows x 8 segs of 16B), 4/thread.
    const int a_seg = tid & 7;
    const int a_r0  = tid >> 3;    // + j*32
    #pragma unroll
    for (int j = 0; j < 4; j++) {
        if (row0 + a_r0 + j * 32 >= K) {   // zero-prefill masked rows, both stages
            const uint32_t d = (a_r0 + j * 32) * 144 + a_seg * 16;
            const uint4 z = make_uint4(0, 0, 0, 0);
            *reinterpret_cast<uint4*>(smem + d + OFF_A) = z;
            *reinterpret_cast<uint4*>(smem + d + STAGE_BYTES + OFF_A) = z;
        }
    }

    // B ownership: 8 slots/thread; slot idx = tid + j*256; k = idx>>5, c4 = idx&31
    const int b_k0 = tid >> 5;      // + j*8
    const int b_c4 = tid & 31;
    const int nch  = Kpad >> 6;

    auto issueA = [&](int ch, uint32_t sbuf) {
        const int kc0 = ch << 6;
        #pragma unroll
        for (int j = 0; j < 4; j++) {
            const int rr = a_r0 + j * 32;
            if (row0 + rr < K)
                cp16(sbuf + rr * 144 + a_seg * 16 + OFF_A,
                     Ag + (size_t)(row0 + rr) * Kpad + kc0 + a_seg * 8);
        }
    };
    // B load for slots [j0, j0+cnt)
    auto ldgB = [&](int ch, int j0, float4* r, int cnt) {
        const int kc0 = ch << 6;
        for (int j = 0; j < cnt; j++) {
            const int k = b_k0 + (j0 + j) * 8;
            r[j] = make_float4(0.f, 0.f, 0.f, 0.f);
            if (kc0 + k < K)
                r[j] = *reinterpret_cast<const float4*>(
                    x + (size_t)(xbase + kc0 + k) * NCOLS + col0 + b_c4 * 4);
        }
    };
    auto stsB = [&](uint32_t off, int j0, const float4* r, int cnt) {
        for (int j = 0; j < cnt; j++) {
            const int k = b_k0 + (j0 + j) * 8;
            *reinterpret_cast<uint2*>(
                smem + off + OFF_B + k * 272 + b_c4 * 8) = cvt4(r[j]);
        }
    };

    float acc[2][8][4];
    #pragma unroll
    for (int mi = 0; mi < 2; mi++)
        #pragma unroll
        for (int ni = 0; ni < 8; ni++)
            #pragma unroll
            for (int q = 0; q < 4; q++) acc[mi][ni][q] = 0.0f;

    const int lr = lane & 15;
    const int lc = lane >> 4;

    // ---- prologue: stage 0 (A async; B inline, both halves)
    issueA(0, sb);
    CP_COMMIT();
    {
        float4 r[4];
        ldgB(0, 0, r, 4); stsB(0, 0, r, 4);
        ldgB(0, 4, r, 4); stsB(0, 4, r, 4);
    }

    for (int ch = 0; ch < nch; ch++) {
        if (ch + 1 < nch) {
            issueA(ch + 1, sb + ((ch + 1) & 1) * STAGE_BYTES);
            CP_COMMIT();
            CP_WAIT1();      // A(ch) landed (in-order group completion)
        } else {
            CP_WAIT0();      // last chunk: drain everything
        }
        __syncthreads();     // stage ch fully visible (A async + B STS)

        // prefetch first half of B(ch+1) NOW; MMA phase hides the latency.
        float4 rp[4];
        const bool more = (ch + 1 < nch);
        if (more) ldgB(ch + 1, 0, rp, 4);

        const uint32_t sbase = sb + (ch & 1) * STAGE_BYTES;
        #pragma unroll
        for (int ks = 0; ks < 4; ks++) {
            uint32_t af[2][4];
            #pragma unroll
            for (int mi = 0; mi < 2; mi++) {
                const uint32_t ao = sbase + OFF_A +
                    ((warp_m * 32 + mi * 16 + lr) * APITCH + ks * 16 + lc * 8) * 2;
                ldsm_x4(af[mi], ao);
            }
            uint32_t bf[4][4];
            #pragma unroll
            for (int p = 0; p < 4; p++) {
                const uint32_t bo = sbase + OFF_B +
                    ((ks * 16 + lr) * BPITCH + warp_n * 64 + p * 16 + lc * 8) * 2;
                ldsm_x4_t(bf[p], bo);
            }
            #pragma unroll
            for (int mi = 0; mi < 2; mi++)
                #pragma unroll
                for (int ni = 0; ni < 8; ni++) {
                    const int p = ni >> 1, s = (ni & 1) * 2;
                    mma_f16(acc[mi][ni], af[mi], bf[p][s], bf[p][s + 1]);
                }
        }

        // store prefetched half, then load+convert+store second half inline
        if (more) {
            const uint32_t off = ((ch + 1) & 1) * STAGE_BYTES;
            stsB(off, 0, rp, 4);
            float4 r2[4];
            ldgB(ch + 1, 4, r2, 4);
            stsB(off, 4, r2, 4);
        }

        __syncthreads();     // stage reads done + next-stage B STS ordered
    }

    // ---- epilogue: masked float2 stores straight from fragments
    const int rbase = row0 + warp_m * 32 + (lane >> 2);
    const int cb    = col0 + warp_n * 64 + (lane & 3) * 2;
    #pragma unroll
    for (int mi = 0; mi < 2; mi++) {
        #pragma unroll
        for (int half = 0; half < 2; half++) {
            const int row = rbase + mi * 16 + half * 8;
            if (row < K) {
                float* dst = out + (size_t)(xbase + row) * NCOLS + cb;
                #pragma unroll
                for (int ni = 0; ni < 8; ni++)
                    *reinterpret_cast<float2*>(dst + ni * 8) =
                        make_float2(acc[mi][ni][half * 2], acc[mi][ni][half * 2 + 1]);
            }
        }
    }
}

extern "C" void kernel_launch(void* const* d_in, const int* in_sizes, int n_in,
                              void* d_out, int out_size)
{
    const float* x = (const float*)d_in[0];
    float* out = (float*)d_out;

    MatPtrs mats;
    for (int i = 0; i < NGROUPS; i++) mats.p[i] = (const float*)d_in[1 + i];

    cudaFuncSetAttribute(bdiag_hmma_kernel,
                         cudaFuncAttributeMaxDynamicSharedMemorySize, SMEM_TOTAL);

    conv_mats_kernel<<<440, 256>>>(mats);
    bdiag_hmma_kernel<<<dim3(NCOLS / 128, NTILES), 256, SMEM_TOTAL>>>(x, out);
}